// round 6
// baseline (speedup 1.0000x reference)
#include <cuda_runtime.h>

#define BATCH  4096
#define TSTEPS 100
#define DDIM   100
#define OOUT   3
#define CW     (BATCH * OOUT)

#define FPSCALE 67108864.0f                       /* 2^26 */
#define INV_FPSCALE 1.490116119384765625e-8f      /* 2^-26 */

// One warp per batch element, 4 timesteps per loop iteration (2 pipelined
// row-pairs). Per lane: 4-bit spike mask -> LDS.128 LUT lookup of fixed-point
// subset sums -> REDUX.SUM per channel. Lane i (<3) owns output channel i.
__global__ __launch_bounds__(128, 8) void leaky_fused(
    const float* __restrict__ x, const float* __restrict__ u,
    const float* __restrict__ W, const float* __restrict__ bias,
    const float* __restrict__ betap, const float* __restrict__ thrp,
    float* __restrict__ out)
{
    // LUT[mask][lane] = (sum w0, sum w1, sum w2, 0) over set bits, fixed-point
    __shared__ int4 lut[16 * 32];
    for (int e = threadIdx.x; e < 16 * 32; e += 128) {
        const int mask = e >> 5;
        const int ln   = e & 31;
        int s0 = 0, s1 = 0, s2 = 0;
        if (ln < (DDIM / 4)) {
            #pragma unroll
            for (int bit = 0; bit < 4; ++bit) {
                if ((mask >> bit) & 1) {
                    const int col = ln * 4 + bit;
                    s0 += __float2int_rn(__ldg(W + 0 * DDIM + col) * FPSCALE);
                    s1 += __float2int_rn(__ldg(W + 1 * DDIM + col) * FPSCALE);
                    s2 += __float2int_rn(__ldg(W + 2 * DDIM + col) * FPSCALE);
                }
            }
        }
        lut[(mask << 5) | ln] = make_int4(s0, s1, s2, 0);
    }
    __syncthreads();

    const int gw   = (blockIdx.x << 2) | (threadIdx.x >> 5);  // batch id
    const int lane = threadIdx.x & 31;

    const float beta = __ldg(betap);
    const float thr  = __ldg(thrp);
    const float bl   = __ldg(bias + ((lane < 2) ? lane : 2)); // lane's channel bias

    const bool act = (lane < (DDIM / 4));   // 25 active load lanes
    const float4 z = make_float4(0.f, 0.f, 0.f, 0.f);

    const float4* __restrict__ xr = (const float4*)(x + (size_t)gw * (TSTEPS * DDIM));
    const float4* __restrict__ ur = (const float4*)(u + (size_t)gw * (TSTEPS * DDIM));

    float* __restrict__ spk = out;
    float* __restrict__ mem = out + (size_t)TSTEPS * CW;

    // two row-pairs in flight: P = rows (t, t+1), Q = rows (t+2, t+3)
    float4 xp0 = z, up0 = z, xp1 = z, up1 = z;
    float4 xq0 = z, uq0 = z, xq1 = z, uq1 = z;
    if (act) {
        xp0 = __ldcs(xr + 0 * (DDIM / 4) + lane);  up0 = __ldcs(ur + 0 * (DDIM / 4) + lane);
        xp1 = __ldcs(xr + 1 * (DDIM / 4) + lane);  up1 = __ldcs(ur + 1 * (DDIM / 4) + lane);
        xq0 = __ldcs(xr + 2 * (DDIM / 4) + lane);  uq0 = __ldcs(ur + 2 * (DDIM / 4) + lane);
        xq1 = __ldcs(xr + 3 * (DDIM / 4) + lane);  uq1 = __ldcs(ur + 3 * (DDIM / 4) + lane);
    }

    float m = 0.f;     // this lane's channel membrane
    float r = 0.f;     // reset = prev spike * thr

    for (int t = 0; t < TSTEPS; t += 4) {
        // ---------------- stage 1: rows t, t+1 (pair P) ----------------
        {
            const int ma = (up0.x < xp0.x) | ((up0.y < xp0.y) << 1)
                         | ((up0.z < xp0.z) << 2) | ((up0.w < xp0.w) << 3);
            const int mb = (up1.x < xp1.x) | ((up1.y < xp1.y) << 1)
                         | ((up1.z < xp1.z) << 2) | ((up1.w < xp1.w) << 3);

            // refill P with rows t+4, t+5 (in flight across stage 2)
            if (act && (t + 4 < TSTEPS)) {
                const int base = (t + 4) * (DDIM / 4) + lane;
                xp0 = __ldcs(xr + base);              up0 = __ldcs(ur + base);
                xp1 = __ldcs(xr + base + (DDIM / 4)); up1 = __ldcs(ur + base + (DDIM / 4));
            }

            const int4 la = lut[(ma << 5) | lane];
            const int4 lb = lut[(mb << 5) | lane];

            const int sa0 = __reduce_add_sync(0xffffffffu, la.x);
            const int sb0 = __reduce_add_sync(0xffffffffu, lb.x);
            const int sa1 = __reduce_add_sync(0xffffffffu, la.y);
            const int sb1 = __reduce_add_sync(0xffffffffu, lb.y);
            const int sa2 = __reduce_add_sync(0xffffffffu, la.z);
            const int sb2 = __reduce_add_sync(0xffffffffu, lb.z);

            const int ia = (lane == 0) ? sa0 : ((lane == 1) ? sa1 : sa2);
            const int ib = (lane == 0) ? sb0 : ((lane == 1) ? sb1 : sb2);
            const float pa = (float)ia * INV_FPSCALE;
            const float pb = (float)ib * INV_FPSCALE;

            // step t
            m = beta * m + (pa + bl) - r;
            float sp = (m - thr > 0.f) ? 1.f : 0.f;
            r = sp * thr;
            if (lane < OOUT) {
                const size_t o = (size_t)t * CW + (size_t)gw * OOUT + lane;
                __stcs(spk + o, sp);
                __stcs(mem + o, m);
            }
            // step t+1
            m = beta * m + (pb + bl) - r;
            sp = (m - thr > 0.f) ? 1.f : 0.f;
            r = sp * thr;
            if (lane < OOUT) {
                const size_t o = (size_t)(t + 1) * CW + (size_t)gw * OOUT + lane;
                __stcs(spk + o, sp);
                __stcs(mem + o, m);
            }
        }
        // ---------------- stage 2: rows t+2, t+3 (pair Q) ----------------
        {
            const int ma = (uq0.x < xq0.x) | ((uq0.y < xq0.y) << 1)
                         | ((uq0.z < xq0.z) << 2) | ((uq0.w < xq0.w) << 3);
            const int mb = (uq1.x < xq1.x) | ((uq1.y < xq1.y) << 1)
                         | ((uq1.z < xq1.z) << 2) | ((uq1.w < xq1.w) << 3);

            // refill Q with rows t+6, t+7
            if (act && (t + 6 < TSTEPS)) {
                const int base = (t + 6) * (DDIM / 4) + lane;
                xq0 = __ldcs(xr + base);              uq0 = __ldcs(ur + base);
                xq1 = __ldcs(xr + base + (DDIM / 4)); uq1 = __ldcs(ur + base + (DDIM / 4));
            }

            const int4 la = lut[(ma << 5) | lane];
            const int4 lb = lut[(mb << 5) | lane];

            const int sa0 = __reduce_add_sync(0xffffffffu, la.x);
            const int sb0 = __reduce_add_sync(0xffffffffu, lb.x);
            const int sa1 = __reduce_add_sync(0xffffffffu, la.y);
            const int sb1 = __reduce_add_sync(0xffffffffu, lb.y);
            const int sa2 = __reduce_add_sync(0xffffffffu, la.z);
            const int sb2 = __reduce_add_sync(0xffffffffu, lb.z);

            const int ia = (lane == 0) ? sa0 : ((lane == 1) ? sa1 : sa2);
            const int ib = (lane == 0) ? sb0 : ((lane == 1) ? sb1 : sb2);
            const float pa = (float)ia * INV_FPSCALE;
            const float pb = (float)ib * INV_FPSCALE;

            // step t+2
            m = beta * m + (pa + bl) - r;
            float sp = (m - thr > 0.f) ? 1.f : 0.f;
            r = sp * thr;
            if (lane < OOUT) {
                const size_t o = (size_t)(t + 2) * CW + (size_t)gw * OOUT + lane;
                __stcs(spk + o, sp);
                __stcs(mem + o, m);
            }
            // step t+3
            m = beta * m + (pb + bl) - r;
            sp = (m - thr > 0.f) ? 1.f : 0.f;
            r = sp * thr;
            if (lane < OOUT) {
                const size_t o = (size_t)(t + 3) * CW + (size_t)gw * OOUT + lane;
                __stcs(spk + o, sp);
                __stcs(mem + o, m);
            }
        }
    }
}

extern "C" void kernel_launch(void* const* d_in, const int* in_sizes, int n_in,
                              void* d_out, int out_size)
{
    const float* x    = (const float*)d_in[0];
    const float* u    = (const float*)d_in[1];
    const float* W    = (const float*)d_in[2];
    const float* bias = (const float*)d_in[3];
    const float* beta = (const float*)d_in[4];
    const float* thr  = (const float*)d_in[5];
    float* out = (float*)d_out;

    leaky_fused<<<BATCH / 4, 128>>>(x, u, W, bias, beta, thr, out);
}